// round 13
// baseline (speedup 1.0000x reference)
#include <cuda_runtime.h>
#include <cuda_fp16.h>

#define NCH 256

// fp16 NHWC copies of the three feature maps.
// offsets (halves): L1=0, L2=33554432, L3=41943040, total 44040192 (88MB)
__device__ __half g_nhwc[44040192];

// ---------------------------------------------------------------------------
// Fused NCHW fp32 -> NHWC fp16 transpose (R12 version, measured 44.7us).
__global__ void __launch_bounds__(256)
nchw_to_nhwc_fused(const float* __restrict__ f1,
                   const float* __restrict__ f2,
                   const float* __restrict__ f3)
{
    __shared__ float tile[64][33];

    int blk = blockIdx.x;
    const float* feat; size_t dst_off; int HW; int t;
    if (blk < 16384)      { feat = f1; dst_off = 0ull;        HW = 65536; t = blk; }
    else if (blk < 20480) { feat = f2; dst_off = 33554432ull; HW = 16384; t = blk - 16384; }
    else                  { feat = f3; dst_off = 41943040ull; HW = 4096;  t = blk - 20480; }

    int nx = HW / 32;
    int cell0 = (t % nx) * 32;
    int rem   = t / nx;
    int c0    = (rem & 3) * 64;
    int b     = rem >> 2;

    int lane = threadIdx.x & 31;
    int wid  = threadIdx.x >> 5;
    const float* src = feat + (size_t)b * NCH * HW;
#pragma unroll
    for (int k = 0; k < 8; k++) {
        int r = wid + k * 8;
        tile[r][lane] = src[(size_t)(c0 + r) * HW + cell0 + lane];
    }
    __syncthreads();
    int cell = threadIdx.x >> 3;
    int c8   = threadIdx.x & 7;
    uint4 u;
    __half2 h;
    h = __floats2half2_rn(tile[c8*8+0][cell], tile[c8*8+1][cell]); u.x = *(unsigned*)&h;
    h = __floats2half2_rn(tile[c8*8+2][cell], tile[c8*8+3][cell]); u.y = *(unsigned*)&h;
    h = __floats2half2_rn(tile[c8*8+4][cell], tile[c8*8+5][cell]); u.z = *(unsigned*)&h;
    h = __floats2half2_rn(tile[c8*8+6][cell], tile[c8*8+7][cell]); u.w = *(unsigned*)&h;
    size_t addr = ((size_t)b * HW + cell0 + cell) * NCH + c0 + c8 * 8;
    reinterpret_cast<uint4*>(g_nhwc + dst_off)[addr >> 3] = u;
}

// ---------------------------------------------------------------------------
// Gather with separable tap dedup: the 2x2 samples' 16 bilinear taps form a
// row-window x col-window tensor product. Merge the two y-samples' row taps
// into up to 4 distinct rows (weights rw[0..3]) and the two x-samples' col
// taps into up to 4 distinct cols (cw[0..3]); load only the (nr x nc) dense
// window (typically 3x3 = 9 loads instead of 16). Validity (x0.5 each axis)
// folded into the separable weights. Loops are warp-uniform; weights packed
// into u64 and extracted by shift (no dynamic-index local memory).

// One axis: from two sample coordinates produce base cell, window extent,
// and 4 merged weights.
template <int DIM>
__device__ __forceinline__ void axis_weights(float p0, float s1, float bin,
                                             int& base, int& n, float* w)
{
    float u0 = fmaf(p0 + 0.25f, bin, s1);
    float u1 = fmaf(p0 + 0.75f, bin, s1);
    float v0 = ((u0 > -1.f) && (u0 < (float)DIM)) ? 0.5f : 0.f;
    float v1 = ((u1 > -1.f) && (u1 < (float)DIM)) ? 0.5f : 0.f;
    float c0 = fminf(fmaxf(u0, 0.f), (float)(DIM - 1));
    float c1 = fminf(fmaxf(u1, 0.f), (float)(DIM - 1));
    int i0 = (int)c0;
    int i1 = (int)c1;
    float l0 = (i0 >= DIM - 1) ? 1.f : c0 - (float)i0;
    float l1 = (i1 >= DIM - 1) ? 1.f : c1 - (float)i1;
    int a0 = min(i0, DIM - 2);
    int a1 = min(i1, DIM - 2);
    int e  = a1 - a0;                      // 0..2 for this problem's rois
    float t00 = (1.f - l0) * v0, t01 = l0 * v0;   // sample0: rows a0, a0+1
    float t10 = (1.f - l1) * v1, t11 = l1 * v1;   // sample1: rows a0+e, a0+e+1
#pragma unroll
    for (int k = 0; k < 4; k++) {
        float acc = 0.f;
        if (k == 0) acc += t00;
        if (k == 1) acc += t01;
        acc += (k == e)     ? t10 : 0.f;
        acc += (k == e + 1) ? t11 : 0.f;
        w[k] = acc;
    }
    base = a0;
    n = e + 2;
}

template <int P, int H, int W>
__device__ __forceinline__ void gather_level(
    const float* __restrict__ rois, float* __restrict__ out_lvl,
    size_t lvl_off, float scale, int pxbase, int npx,
    unsigned* __restrict__ sacc)
{
    constexpr int pixels = P * P;
    int tid  = threadIdx.x;
    int wid  = tid >> 5;
    int lane = tid & 31;

    for (int j = 0; j < 4; j++) {
        int pxl = j * 8 + wid;
        int gpx = pxbase + pxl;
        __half2 a0 = __float2half2_rn(0.f), a1 = a0, a2 = a0, a3 = a0;
        if (gpx < npx) {
            int n  = gpx / pixels;
            int p  = gpx - n * pixels;
            int ph = p / P;
            int pw = p - ph * P;
            const float* r = rois + n * 5;
            int   bi = (int)r[0];
            float x1 = fmaf(r[1], scale, -0.5f);
            float y1 = fmaf(r[2], scale, -0.5f);
            float bw = (fmaf(r[3], scale, -0.5f) - x1) * (1.0f / (float)P);
            float bh = (fmaf(r[4], scale, -0.5f) - y1) * (1.0f / (float)P);

            int ybase, xbase, nr, nc;
            float rw[4], cw[4];
            axis_weights<H>((float)ph, y1, bh, ybase, nr, rw);
            axis_weights<W>((float)pw, x1, bw, xbase, nc, cw);

            // pack weights as fp16 for shift-extraction in the dynamic loops
            __half2 rlo = __floats2half2_rn(rw[0], rw[1]);
            __half2 rhi = __floats2half2_rn(rw[2], rw[3]);
            __half2 clo = __floats2half2_rn(cw[0], cw[1]);
            __half2 chi = __floats2half2_rn(cw[2], cw[3]);
            unsigned long long rwp = *(unsigned*)&rlo |
                                     ((unsigned long long)(*(unsigned*)&rhi) << 32);
            unsigned long long cwp = *(unsigned*)&clo |
                                     ((unsigned long long)(*(unsigned*)&chi) << 32);

            const __half* base = g_nhwc + lvl_off
                               + ((size_t)bi * ((size_t)H * W)
                                  + (size_t)ybase * W + xbase) * NCH + lane * 8;

            for (int rr = 0; rr < nr; rr++) {
                __half2 rwh = __half2half2(
                    __ushort_as_half((unsigned short)(rwp >> (16 * rr))));
                __half2 q0 = __float2half2_rn(0.f), q1 = q0, q2 = q0, q3 = q0;
                const __half* rp = base + (size_t)rr * W * NCH;
                for (int cc = 0; cc < nc; cc++) {
                    __half2 cwh = __half2half2(
                        __ushort_as_half((unsigned short)(cwp >> (16 * cc))));
                    uint4 v = __ldg(reinterpret_cast<const uint4*>(rp + cc * NCH));
                    const __half2* hh = reinterpret_cast<const __half2*>(&v);
                    q0 = __hfma2(cwh, hh[0], q0);
                    q1 = __hfma2(cwh, hh[1], q1);
                    q2 = __hfma2(cwh, hh[2], q2);
                    q3 = __hfma2(cwh, hh[3], q3);
                }
                a0 = __hfma2(rwh, q0, a0);
                a1 = __hfma2(rwh, q1, a1);
                a2 = __hfma2(rwh, q2, a2);
                a3 = __hfma2(rwh, q3, a3);
            }
        }
        int col = pxl ^ lane;
        sacc[(4 * lane + 0) * 32 + col] = *(unsigned*)&a0;
        sacc[(4 * lane + 1) * 32 + col] = *(unsigned*)&a1;
        sacc[(4 * lane + 2) * 32 + col] = *(unsigned*)&a2;
        sacc[(4 * lane + 3) * 32 + col] = *(unsigned*)&a3;
    }
    __syncthreads();

    // store phase: lanes along pixels -> coalesced NCHW writes
    int pxlane = tid & 31;
    int gpx = pxbase + pxlane;
    if (gpx < npx) {
        int n = gpx / pixels;
        int p = gpx - n * pixels;
        float* ob = out_lvl + (size_t)n * NCH * pixels + p;
        int pp0 = (tid >> 5) * 16;
#pragma unroll
        for (int i = 0; i < 16; i++) {
            int pp = pp0 + i;
            unsigned u = sacc[pp * 32 + (pxlane ^ (pp >> 2))];
            __half2 h = *(__half2*)&u;
            int c = 2 * pp;
            ob[(size_t)c       * pixels] = __low2float(h);
            ob[(size_t)(c + 1) * pixels] = __high2float(h);
        }
    }
}

__global__ void __launch_bounds__(256)
roi_gather_kernel(const float* __restrict__ rois, float* __restrict__ out,
                  int N, int nb1, int nb2)
{
    __shared__ unsigned sacc[128 * 32];   // 16KB
    int blk = blockIdx.x;
    if (blk < nb1) {
        gather_level<28, 256, 256>(rois, out, 0ull, 0.25f,
                                   blk * 32, N * 784, sacc);
    } else if (blk < nb1 + nb2) {
        float* o2 = out + (size_t)N * NCH * 784;
        gather_level<14, 128, 128>(rois, o2, 33554432ull, 0.125f,
                                   (blk - nb1) * 32, N * 196, sacc);
    } else {
        float* o3 = out + (size_t)N * NCH * (784 + 196);
        gather_level<7, 64, 64>(rois, o3, 41943040ull, 0.0625f,
                                (blk - nb1 - nb2) * 32, N * 49, sacc);
    }
}

// ---------------------------------------------------------------------------
extern "C" void kernel_launch(void* const* d_in, const int* in_sizes, int n_in,
                              void* d_out, int out_size)
{
    const float* feat1 = (const float*)d_in[0];  // (2,256,256,256)
    const float* feat2 = (const float*)d_in[1];  // (2,256,128,128)
    const float* feat3 = (const float*)d_in[2];  // (2,256,64,64)
    const float* rois  = (const float*)d_in[3];  // (N,5)
    float* out = (float*)d_out;

    const int N = in_sizes[3] / 5;

    // 1) fused transpose: 16384 (L1) + 4096 (L2) + 1024 (L3) blocks
    nchw_to_nhwc_fused<<<21504, 256>>>(feat1, feat2, feat3);

    // 2) fused gather over all three levels
    int nb1 = (N * 784 + 31) / 32;
    int nb2 = (N * 196 + 31) / 32;
    int nb3 = (N * 49  + 31) / 32;
    roi_gather_kernel<<<nb1 + nb2 + nb3, 256>>>(rois, out, N, nb1, nb2);
}

// round 14
// speedup vs baseline: 1.1999x; 1.1999x over previous
#include <cuda_runtime.h>
#include <cuda_fp16.h>

#define NCH 256

// fp16 NHWC copies of the three feature maps.
// offsets (halves): L1=0, L2=33554432, L3=41943040, total 44040192 (88MB)
__device__ __half g_nhwc[44040192];

// ---------------------------------------------------------------------------
// Fused NCHW fp32 -> NHWC fp16 transpose (R12 version, measured 44.7us).
__global__ void __launch_bounds__(256)
nchw_to_nhwc_fused(const float* __restrict__ f1,
                   const float* __restrict__ f2,
                   const float* __restrict__ f3)
{
    __shared__ float tile[64][33];

    int blk = blockIdx.x;
    const float* feat; size_t dst_off; int HW; int t;
    if (blk < 16384)      { feat = f1; dst_off = 0ull;        HW = 65536; t = blk; }
    else if (blk < 20480) { feat = f2; dst_off = 33554432ull; HW = 16384; t = blk - 16384; }
    else                  { feat = f3; dst_off = 41943040ull; HW = 4096;  t = blk - 20480; }

    int nx = HW / 32;
    int cell0 = (t % nx) * 32;
    int rem   = t / nx;
    int c0    = (rem & 3) * 64;
    int b     = rem >> 2;

    int lane = threadIdx.x & 31;
    int wid  = threadIdx.x >> 5;
    const float* src = feat + (size_t)b * NCH * HW;
#pragma unroll
    for (int k = 0; k < 8; k++) {
        int r = wid + k * 8;
        tile[r][lane] = src[(size_t)(c0 + r) * HW + cell0 + lane];
    }
    __syncthreads();
    int cell = threadIdx.x >> 3;
    int c8   = threadIdx.x & 7;
    uint4 u;
    __half2 h;
    h = __floats2half2_rn(tile[c8*8+0][cell], tile[c8*8+1][cell]); u.x = *(unsigned*)&h;
    h = __floats2half2_rn(tile[c8*8+2][cell], tile[c8*8+3][cell]); u.y = *(unsigned*)&h;
    h = __floats2half2_rn(tile[c8*8+4][cell], tile[c8*8+5][cell]); u.z = *(unsigned*)&h;
    h = __floats2half2_rn(tile[c8*8+6][cell], tile[c8*8+7][cell]); u.w = *(unsigned*)&h;
    size_t addr = ((size_t)b * HW + cell0 + cell) * NCH + c0 + c8 * 8;
    reinterpret_cast<uint4*>(g_nhwc + dst_off)[addr >> 3] = u;
}

// ---------------------------------------------------------------------------
// Gather with STATIC separable tap dedup. The 2x2 samples' 16 bilinear taps
// = (row taps) x (col taps); merged per axis into <=4 weights over a dense
// window. Core is a fully-unrolled 3x3 (covers extent e<=1 on both axes);
// the rare e=2 axis adds a warp-uniform predicated 4th col/row. Unused core
// weights are exactly 0 and their addresses clamped in-bounds. Weights live
// in named half2 registers — no dynamic indexing, no packing.

template <int DIM>
__device__ __forceinline__ void axis_weights(float p0, float s1, float bin,
                                             int& base, bool& has4,
                                             float& w0, float& w1,
                                             float& w2, float& w3)
{
    float u0 = fmaf(p0 + 0.25f, bin, s1);
    float u1 = fmaf(p0 + 0.75f, bin, s1);
    float v0 = ((u0 > -1.f) && (u0 < (float)DIM)) ? 0.5f : 0.f;
    float v1 = ((u1 > -1.f) && (u1 < (float)DIM)) ? 0.5f : 0.f;
    float c0 = fminf(fmaxf(u0, 0.f), (float)(DIM - 1));
    float c1 = fminf(fmaxf(u1, 0.f), (float)(DIM - 1));
    int i0 = (int)c0;
    int i1 = (int)c1;
    float l0 = (i0 >= DIM - 1) ? 1.f : c0 - (float)i0;
    float l1 = (i1 >= DIM - 1) ? 1.f : c1 - (float)i1;
    int a0 = min(i0, DIM - 2);
    int a1 = min(i1, DIM - 2);
    int e  = a1 - a0;                       // 0, 1, or 2
    float t00 = (1.f - l0) * v0, t01 = l0 * v0;  // sample0 -> slots 0,1
    float t10 = (1.f - l1) * v1, t11 = l1 * v1;  // sample1 -> slots e,e+1
    w0 = t00 + ((e == 0) ? t10 : 0.f);
    w1 = t01 + ((e == 0) ? t11 : ((e == 1) ? t10 : 0.f));
    w2 = (e == 1) ? t11 : ((e == 2) ? t10 : 0.f);
    w3 = (e == 2) ? t11 : 0.f;
    base = a0;
    has4 = (e == 2);
}

// one 16B tap load + 4-wide HFMA2 into q0..q3 with column weight cwh
#define CTAP(ptr, cwh) do {                                                  \
    uint4 _v = __ldg(reinterpret_cast<const uint4*>(ptr));                   \
    const __half2* _h = reinterpret_cast<const __half2*>(&_v);               \
    q0 = __hfma2(cwh, _h[0], q0); q1 = __hfma2(cwh, _h[1], q1);              \
    q2 = __hfma2(cwh, _h[2], q2); q3 = __hfma2(cwh, _h[3], q3);              \
} while (0)

template <int P, int H, int W>
__device__ __forceinline__ void gather_level(
    const float* __restrict__ rois, float* __restrict__ out_lvl,
    size_t lvl_off, float scale, int pxbase, int npx,
    unsigned* __restrict__ sacc)
{
    constexpr int pixels = P * P;
    int tid  = threadIdx.x;
    int wid  = tid >> 5;
    int lane = tid & 31;

    for (int j = 0; j < 4; j++) {
        int pxl = j * 8 + wid;
        int gpx = pxbase + pxl;
        __half2 a0 = __float2half2_rn(0.f), a1 = a0, a2 = a0, a3 = a0;
        if (gpx < npx) {
            int n  = gpx / pixels;
            int p  = gpx - n * pixels;
            int ph = p / P;
            int pw = p - ph * P;
            const float* r = rois + n * 5;
            int   bi = (int)r[0];
            float x1 = fmaf(r[1], scale, -0.5f);
            float y1 = fmaf(r[2], scale, -0.5f);
            float bw = (fmaf(r[3], scale, -0.5f) - x1) * (1.0f / (float)P);
            float bh = (fmaf(r[4], scale, -0.5f) - y1) * (1.0f / (float)P);

            int ybase, xbase; bool ry4, cx4;
            float rwf0, rwf1, rwf2, rwf3, cwf0, cwf1, cwf2, cwf3;
            axis_weights<H>((float)ph, y1, bh, ybase, ry4, rwf0, rwf1, rwf2, rwf3);
            axis_weights<W>((float)pw, x1, bw, xbase, cx4, cwf0, cwf1, cwf2, cwf3);

            __half2 rw0 = __float2half2_rn(rwf0), rw1 = __float2half2_rn(rwf1);
            __half2 rw2 = __float2half2_rn(rwf2), rw3 = __float2half2_rn(rwf3);
            __half2 cw0 = __float2half2_rn(cwf0), cw1 = __float2half2_rn(cwf1);
            __half2 cw2 = __float2half2_rn(cwf2), cw3 = __float2half2_rn(cwf3);

            const __half* rp0 = g_nhwc + lvl_off
                              + ((size_t)bi * ((size_t)H * W)
                                 + (size_t)ybase * W + xbase) * NCH + lane * 8;
            // clamped in-tile offsets (weight-0 slots load safely in-bounds)
            int o1  = (min(xbase + 1, W - 1) - xbase) * NCH;
            int o2  = (min(xbase + 2, W - 1) - xbase) * NCH;
            int ro1 = (min(ybase + 1, H - 1) - ybase) * W * NCH;
            int ro2 = (min(ybase + 2, H - 1) - ybase) * W * NCH;

            __half2 z = __float2half2_rn(0.f);
            // row 0
            {
                __half2 q0 = z, q1 = z, q2 = z, q3 = z;
                CTAP(rp0,      cw0);
                CTAP(rp0 + o1, cw1);
                CTAP(rp0 + o2, cw2);
                if (cx4) CTAP(rp0 + 3 * NCH, cw3);
                a0 = __hfma2(rw0, q0, a0); a1 = __hfma2(rw0, q1, a1);
                a2 = __hfma2(rw0, q2, a2); a3 = __hfma2(rw0, q3, a3);
            }
            // row 1
            {
                const __half* rp = rp0 + ro1;
                __half2 q0 = z, q1 = z, q2 = z, q3 = z;
                CTAP(rp,      cw0);
                CTAP(rp + o1, cw1);
                CTAP(rp + o2, cw2);
                if (cx4) CTAP(rp + 3 * NCH, cw3);
                a0 = __hfma2(rw1, q0, a0); a1 = __hfma2(rw1, q1, a1);
                a2 = __hfma2(rw1, q2, a2); a3 = __hfma2(rw1, q3, a3);
            }
            // row 2
            {
                const __half* rp = rp0 + ro2;
                __half2 q0 = z, q1 = z, q2 = z, q3 = z;
                CTAP(rp,      cw0);
                CTAP(rp + o1, cw1);
                CTAP(rp + o2, cw2);
                if (cx4) CTAP(rp + 3 * NCH, cw3);
                a0 = __hfma2(rw2, q0, a0); a1 = __hfma2(rw2, q1, a1);
                a2 = __hfma2(rw2, q2, a2); a3 = __hfma2(rw2, q3, a3);
            }
            // rare row 3 (e_y == 2; addresses valid by construction)
            if (ry4) {
                const __half* rp = rp0 + 3 * W * NCH;
                __half2 q0 = z, q1 = z, q2 = z, q3 = z;
                CTAP(rp,      cw0);
                CTAP(rp + o1, cw1);
                CTAP(rp + o2, cw2);
                if (cx4) CTAP(rp + 3 * NCH, cw3);
                a0 = __hfma2(rw3, q0, a0); a1 = __hfma2(rw3, q1, a1);
                a2 = __hfma2(rw3, q2, a2); a3 = __hfma2(rw3, q3, a3);
            }
        }
        int col = pxl ^ lane;
        sacc[(4 * lane + 0) * 32 + col] = *(unsigned*)&a0;
        sacc[(4 * lane + 1) * 32 + col] = *(unsigned*)&a1;
        sacc[(4 * lane + 2) * 32 + col] = *(unsigned*)&a2;
        sacc[(4 * lane + 3) * 32 + col] = *(unsigned*)&a3;
    }
    __syncthreads();

    // store phase: lanes along pixels -> coalesced NCHW writes
    int pxlane = tid & 31;
    int gpx = pxbase + pxlane;
    if (gpx < npx) {
        int n = gpx / pixels;
        int p = gpx - n * pixels;
        float* ob = out_lvl + (size_t)n * NCH * pixels + p;
        int pp0 = (tid >> 5) * 16;
#pragma unroll
        for (int i = 0; i < 16; i++) {
            int pp = pp0 + i;
            unsigned u = sacc[pp * 32 + (pxlane ^ (pp >> 2))];
            __half2 h = *(__half2*)&u;
            int c = 2 * pp;
            ob[(size_t)c       * pixels] = __low2float(h);
            ob[(size_t)(c + 1) * pixels] = __high2float(h);
        }
    }
}

__global__ void __launch_bounds__(256)
roi_gather_kernel(const float* __restrict__ rois, float* __restrict__ out,
                  int N, int nb1, int nb2)
{
    __shared__ unsigned sacc[128 * 32];   // 16KB
    int blk = blockIdx.x;
    if (blk < nb1) {
        gather_level<28, 256, 256>(rois, out, 0ull, 0.25f,
                                   blk * 32, N * 784, sacc);
    } else if (blk < nb1 + nb2) {
        float* o2 = out + (size_t)N * NCH * 784;
        gather_level<14, 128, 128>(rois, o2, 33554432ull, 0.125f,
                                   (blk - nb1) * 32, N * 196, sacc);
    } else {
        float* o3 = out + (size_t)N * NCH * (784 + 196);
        gather_level<7, 64, 64>(rois, o3, 41943040ull, 0.0625f,
                                (blk - nb1 - nb2) * 32, N * 49, sacc);
    }
}

// ---------------------------------------------------------------------------
extern "C" void kernel_launch(void* const* d_in, const int* in_sizes, int n_in,
                              void* d_out, int out_size)
{
    const float* feat1 = (const float*)d_in[0];  // (2,256,256,256)
    const float* feat2 = (const float*)d_in[1];  // (2,256,128,128)
    const float* feat3 = (const float*)d_in[2];  // (2,256,64,64)
    const float* rois  = (const float*)d_in[3];  // (N,5)
    float* out = (float*)d_out;

    const int N = in_sizes[3] / 5;

    // 1) fused transpose: 16384 (L1) + 4096 (L2) + 1024 (L3) blocks
    nchw_to_nhwc_fused<<<21504, 256>>>(feat1, feat2, feat3);

    // 2) fused gather over all three levels
    int nb1 = (N * 784 + 31) / 32;
    int nb2 = (N * 196 + 31) / 32;
    int nb3 = (N * 49  + 31) / 32;
    roi_gather_kernel<<<nb1 + nb2 + nb3, 256>>>(rois, out, N, nb1, nb2);
}

// round 15
// speedup vs baseline: 1.2366x; 1.0306x over previous
#include <cuda_runtime.h>
#include <cuda_fp16.h>

#define NCH 256

// fp16 NHWC copies of the three feature maps.
// offsets (halves): L1=0, L2=33554432, L3=41943040, total 44040192 (88MB)
__device__ __half g_nhwc[44040192];

// ---------------------------------------------------------------------------
// Fused NCHW fp32 -> NHWC fp16 transpose (R12 version, measured 44.7us).
__global__ void __launch_bounds__(256)
nchw_to_nhwc_fused(const float* __restrict__ f1,
                   const float* __restrict__ f2,
                   const float* __restrict__ f3)
{
    __shared__ float tile[64][33];

    int blk = blockIdx.x;
    const float* feat; size_t dst_off; int HW; int t;
    if (blk < 16384)      { feat = f1; dst_off = 0ull;        HW = 65536; t = blk; }
    else if (blk < 20480) { feat = f2; dst_off = 33554432ull; HW = 16384; t = blk - 16384; }
    else                  { feat = f3; dst_off = 41943040ull; HW = 4096;  t = blk - 20480; }

    int nx = HW / 32;
    int cell0 = (t % nx) * 32;
    int rem   = t / nx;
    int c0    = (rem & 3) * 64;
    int b     = rem >> 2;

    int lane = threadIdx.x & 31;
    int wid  = threadIdx.x >> 5;
    const float* src = feat + (size_t)b * NCH * HW;
#pragma unroll
    for (int k = 0; k < 8; k++) {
        int r = wid + k * 8;
        tile[r][lane] = src[(size_t)(c0 + r) * HW + cell0 + lane];
    }
    __syncthreads();
    int cell = threadIdx.x >> 3;
    int c8   = threadIdx.x & 7;
    uint4 u;
    __half2 h;
    h = __floats2half2_rn(tile[c8*8+0][cell], tile[c8*8+1][cell]); u.x = *(unsigned*)&h;
    h = __floats2half2_rn(tile[c8*8+2][cell], tile[c8*8+3][cell]); u.y = *(unsigned*)&h;
    h = __floats2half2_rn(tile[c8*8+4][cell], tile[c8*8+5][cell]); u.z = *(unsigned*)&h;
    h = __floats2half2_rn(tile[c8*8+6][cell], tile[c8*8+7][cell]); u.w = *(unsigned*)&h;
    size_t addr = ((size_t)b * HW + cell0 + cell) * NCH + c0 + c8 * 8;
    reinterpret_cast<uint4*>(g_nhwc + dst_off)[addr >> 3] = u;
}

// ---------------------------------------------------------------------------
// Gather with static separable tap dedup (R14) + warp-uniform INTERIOR fast
// path: when the 3x3 window needs no clamping and no 4th row/col (~75% of
// pixels; uniform across the warp since warp = one pixel), all 9 taps use
// compile-time immediate offsets from one base pointer. Slow path = R14
// general code. Same weights/arithmetic order in both paths.

template <int DIM>
__device__ __forceinline__ void axis_weights(float p0, float s1, float bin,
                                             int& base, bool& has4,
                                             float& w0, float& w1,
                                             float& w2, float& w3)
{
    float u0 = fmaf(p0 + 0.25f, bin, s1);
    float u1 = fmaf(p0 + 0.75f, bin, s1);
    float v0 = ((u0 > -1.f) && (u0 < (float)DIM)) ? 0.5f : 0.f;
    float v1 = ((u1 > -1.f) && (u1 < (float)DIM)) ? 0.5f : 0.f;
    float c0 = fminf(fmaxf(u0, 0.f), (float)(DIM - 1));
    float c1 = fminf(fmaxf(u1, 0.f), (float)(DIM - 1));
    int i0 = (int)c0;
    int i1 = (int)c1;
    float l0 = (i0 >= DIM - 1) ? 1.f : c0 - (float)i0;
    float l1 = (i1 >= DIM - 1) ? 1.f : c1 - (float)i1;
    int a0 = min(i0, DIM - 2);
    int a1 = min(i1, DIM - 2);
    int e  = a1 - a0;                       // 0, 1, or 2
    float t00 = (1.f - l0) * v0, t01 = l0 * v0;
    float t10 = (1.f - l1) * v1, t11 = l1 * v1;
    w0 = t00 + ((e == 0) ? t10 : 0.f);
    w1 = t01 + ((e == 0) ? t11 : ((e == 1) ? t10 : 0.f));
    w2 = (e == 1) ? t11 : ((e == 2) ? t10 : 0.f);
    w3 = (e == 2) ? t11 : 0.f;
    base = a0;
    has4 = (e == 2);
}

#define CTAP(ptr, cwh) do {                                                  \
    uint4 _v = __ldg(reinterpret_cast<const uint4*>(ptr));                   \
    const __half2* _h = reinterpret_cast<const __half2*>(&_v);               \
    q0 = __hfma2(cwh, _h[0], q0); q1 = __hfma2(cwh, _h[1], q1);              \
    q2 = __hfma2(cwh, _h[2], q2); q3 = __hfma2(cwh, _h[3], q3);              \
} while (0)

#define ROWCOMBINE(rwh) do {                                                 \
    a0 = __hfma2(rwh, q0, a0); a1 = __hfma2(rwh, q1, a1);                    \
    a2 = __hfma2(rwh, q2, a2); a3 = __hfma2(rwh, q3, a3);                    \
} while (0)

template <int P, int H, int W>
__device__ __forceinline__ void gather_level(
    const float* __restrict__ rois, float* __restrict__ out_lvl,
    size_t lvl_off, float scale, int pxbase, int npx,
    unsigned* __restrict__ sacc)
{
    constexpr int pixels = P * P;
    int tid  = threadIdx.x;
    int wid  = tid >> 5;
    int lane = tid & 31;

    for (int j = 0; j < 4; j++) {
        int pxl = j * 8 + wid;
        int gpx = pxbase + pxl;
        __half2 a0 = __float2half2_rn(0.f), a1 = a0, a2 = a0, a3 = a0;
        if (gpx < npx) {
            int n  = gpx / pixels;
            int p  = gpx - n * pixels;
            int ph = p / P;
            int pw = p - ph * P;
            const float* r = rois + n * 5;
            int   bi = (int)r[0];
            float x1 = fmaf(r[1], scale, -0.5f);
            float y1 = fmaf(r[2], scale, -0.5f);
            float bw = (fmaf(r[3], scale, -0.5f) - x1) * (1.0f / (float)P);
            float bh = (fmaf(r[4], scale, -0.5f) - y1) * (1.0f / (float)P);

            int ybase, xbase; bool ry4, cx4;
            float rwf0, rwf1, rwf2, rwf3, cwf0, cwf1, cwf2, cwf3;
            axis_weights<H>((float)ph, y1, bh, ybase, ry4, rwf0, rwf1, rwf2, rwf3);
            axis_weights<W>((float)pw, x1, bw, xbase, cx4, cwf0, cwf1, cwf2, cwf3);

            __half2 rw0 = __float2half2_rn(rwf0), rw1 = __float2half2_rn(rwf1);
            __half2 rw2 = __float2half2_rn(rwf2), rw3 = __float2half2_rn(rwf3);
            __half2 cw0 = __float2half2_rn(cwf0), cw1 = __float2half2_rn(cwf1);
            __half2 cw2 = __float2half2_rn(cwf2), cw3 = __float2half2_rn(cwf3);

            const __half* rp0 = g_nhwc + lvl_off
                              + ((size_t)bi * ((size_t)H * W)
                                 + (size_t)ybase * W + xbase) * NCH + lane * 8;
            __half2 z = __float2half2_rn(0.f);

            // interior fast path (warp-uniform: geometry identical per warp)
            if (!ry4 && !cx4 && xbase <= W - 3 && ybase <= H - 3) {
                {
                    __half2 q0 = z, q1 = z, q2 = z, q3 = z;
                    CTAP(rp0,           cw0);
                    CTAP(rp0 + NCH,     cw1);
                    CTAP(rp0 + 2 * NCH, cw2);
                    ROWCOMBINE(rw0);
                }
                {
                    const __half* rp = rp0 + W * NCH;
                    __half2 q0 = z, q1 = z, q2 = z, q3 = z;
                    CTAP(rp,           cw0);
                    CTAP(rp + NCH,     cw1);
                    CTAP(rp + 2 * NCH, cw2);
                    ROWCOMBINE(rw1);
                }
                {
                    const __half* rp = rp0 + 2 * W * NCH;
                    __half2 q0 = z, q1 = z, q2 = z, q3 = z;
                    CTAP(rp,           cw0);
                    CTAP(rp + NCH,     cw1);
                    CTAP(rp + 2 * NCH, cw2);
                    ROWCOMBINE(rw2);
                }
            } else {
                // general path: clamped offsets + optional 4th row/col
                int o2  = (min(xbase + 2, W - 1) - xbase) * NCH;
                int ro1 = (min(ybase + 1, H - 1) - ybase) * W * NCH;
                int ro2 = (min(ybase + 2, H - 1) - ybase) * W * NCH;
                {
                    __half2 q0 = z, q1 = z, q2 = z, q3 = z;
                    CTAP(rp0,       cw0);
                    CTAP(rp0 + NCH, cw1);
                    CTAP(rp0 + o2,  cw2);
                    if (cx4) CTAP(rp0 + 3 * NCH, cw3);
                    ROWCOMBINE(rw0);
                }
                {
                    const __half* rp = rp0 + ro1;
                    __half2 q0 = z, q1 = z, q2 = z, q3 = z;
                    CTAP(rp,       cw0);
                    CTAP(rp + NCH, cw1);
                    CTAP(rp + o2,  cw2);
                    if (cx4) CTAP(rp + 3 * NCH, cw3);
                    ROWCOMBINE(rw1);
                }
                {
                    const __half* rp = rp0 + ro2;
                    __half2 q0 = z, q1 = z, q2 = z, q3 = z;
                    CTAP(rp,       cw0);
                    CTAP(rp + NCH, cw1);
                    CTAP(rp + o2,  cw2);
                    if (cx4) CTAP(rp + 3 * NCH, cw3);
                    ROWCOMBINE(rw2);
                }
                if (ry4) {
                    const __half* rp = rp0 + 3 * W * NCH;
                    __half2 q0 = z, q1 = z, q2 = z, q3 = z;
                    CTAP(rp,       cw0);
                    CTAP(rp + NCH, cw1);
                    CTAP(rp + o2,  cw2);
                    if (cx4) CTAP(rp + 3 * NCH, cw3);
                    ROWCOMBINE(rw3);
                }
            }
        }
        int col = pxl ^ lane;
        sacc[(4 * lane + 0) * 32 + col] = *(unsigned*)&a0;
        sacc[(4 * lane + 1) * 32 + col] = *(unsigned*)&a1;
        sacc[(4 * lane + 2) * 32 + col] = *(unsigned*)&a2;
        sacc[(4 * lane + 3) * 32 + col] = *(unsigned*)&a3;
    }
    __syncthreads();

    // store phase: lanes along pixels -> coalesced NCHW writes
    int pxlane = tid & 31;
    int gpx = pxbase + pxlane;
    if (gpx < npx) {
        int n = gpx / pixels;
        int p = gpx - n * pixels;
        float* ob = out_lvl + (size_t)n * NCH * pixels + p;
        int pp0 = (tid >> 5) * 16;
#pragma unroll
        for (int i = 0; i < 16; i++) {
            int pp = pp0 + i;
            unsigned u = sacc[pp * 32 + (pxlane ^ (pp >> 2))];
            __half2 h = *(__half2*)&u;
            int c = 2 * pp;
            ob[(size_t)c       * pixels] = __low2float(h);
            ob[(size_t)(c + 1) * pixels] = __high2float(h);
        }
    }
}

__global__ void __launch_bounds__(256)
roi_gather_kernel(const float* __restrict__ rois, float* __restrict__ out,
                  int N, int nb1, int nb2)
{
    __shared__ unsigned sacc[128 * 32];   // 16KB
    int blk = blockIdx.x;
    if (blk < nb1) {
        gather_level<28, 256, 256>(rois, out, 0ull, 0.25f,
                                   blk * 32, N * 784, sacc);
    } else if (blk < nb1 + nb2) {
        float* o2 = out + (size_t)N * NCH * 784;
        gather_level<14, 128, 128>(rois, o2, 33554432ull, 0.125f,
                                   (blk - nb1) * 32, N * 196, sacc);
    } else {
        float* o3 = out + (size_t)N * NCH * (784 + 196);
        gather_level<7, 64, 64>(rois, o3, 41943040ull, 0.0625f,
                                (blk - nb1 - nb2) * 32, N * 49, sacc);
    }
}

// ---------------------------------------------------------------------------
extern "C" void kernel_launch(void* const* d_in, const int* in_sizes, int n_in,
                              void* d_out, int out_size)
{
    const float* feat1 = (const float*)d_in[0];  // (2,256,256,256)
    const float* feat2 = (const float*)d_in[1];  // (2,256,128,128)
    const float* feat3 = (const float*)d_in[2];  // (2,256,64,64)
    const float* rois  = (const float*)d_in[3];  // (N,5)
    float* out = (float*)d_out;

    const int N = in_sizes[3] / 5;

    // 1) fused transpose: 16384 (L1) + 4096 (L2) + 1024 (L3) blocks
    nchw_to_nhwc_fused<<<21504, 256>>>(feat1, feat2, feat3);

    // 2) fused gather over all three levels
    int nb1 = (N * 784 + 31) / 32;
    int nb2 = (N * 196 + 31) / 32;
    int nb3 = (N * 49  + 31) / 32;
    roi_gather_kernel<<<nb1 + nb2 + nb3, 256>>>(rois, out, N, nb1, nb2);
}

// round 16
// speedup vs baseline: 1.2893x; 1.0426x over previous
#include <cuda_runtime.h>
#include <cuda_fp16.h>

#define NCH 256

// fp16 NHWC copies of the three feature maps.
// offsets (halves): L1=0, L2=33554432, L3=41943040, total 44040192 (88MB)
__device__ __half g_nhwc[44040192];

// ---------------------------------------------------------------------------
// Fused NCHW fp32 -> NHWC fp16 transpose (R12 version, measured 44.7us).
__global__ void __launch_bounds__(256)
nchw_to_nhwc_fused(const float* __restrict__ f1,
                   const float* __restrict__ f2,
                   const float* __restrict__ f3)
{
    __shared__ float tile[64][33];

    int blk = blockIdx.x;
    const float* feat; size_t dst_off; int HW; int t;
    if (blk < 16384)      { feat = f1; dst_off = 0ull;        HW = 65536; t = blk; }
    else if (blk < 20480) { feat = f2; dst_off = 33554432ull; HW = 16384; t = blk - 16384; }
    else                  { feat = f3; dst_off = 41943040ull; HW = 4096;  t = blk - 20480; }

    int nx = HW / 32;
    int cell0 = (t % nx) * 32;
    int rem   = t / nx;
    int c0    = (rem & 3) * 64;
    int b     = rem >> 2;

    int lane = threadIdx.x & 31;
    int wid  = threadIdx.x >> 5;
    const float* src = feat + (size_t)b * NCH * HW;
#pragma unroll
    for (int k = 0; k < 8; k++) {
        int r = wid + k * 8;
        tile[r][lane] = src[(size_t)(c0 + r) * HW + cell0 + lane];
    }
    __syncthreads();
    int cell = threadIdx.x >> 3;
    int c8   = threadIdx.x & 7;
    uint4 u;
    __half2 h;
    h = __floats2half2_rn(tile[c8*8+0][cell], tile[c8*8+1][cell]); u.x = *(unsigned*)&h;
    h = __floats2half2_rn(tile[c8*8+2][cell], tile[c8*8+3][cell]); u.y = *(unsigned*)&h;
    h = __floats2half2_rn(tile[c8*8+4][cell], tile[c8*8+5][cell]); u.z = *(unsigned*)&h;
    h = __floats2half2_rn(tile[c8*8+6][cell], tile[c8*8+7][cell]); u.w = *(unsigned*)&h;
    size_t addr = ((size_t)b * HW + cell0 + cell) * NCH + c0 + c8 * 8;
    reinterpret_cast<uint4*>(g_nhwc + dst_off)[addr >> 3] = u;
}

// ---------------------------------------------------------------------------
// Gather, static separable dedup (R14/R15) + SHFL-distributed geometry:
// lane l computes FULL geometry for pixel j=(l&3) once; each j-iteration
// broadcasts the packed results (base offset, packed half weights, flags,
// slow-path offsets) with __shfl_sync instead of recomputing ~90 ALU ops.

template <int DIM>
__device__ __forceinline__ void axis_weights(float p0, float s1, float bin,
                                             int& base, bool& has4,
                                             float& w0, float& w1,
                                             float& w2, float& w3)
{
    float u0 = fmaf(p0 + 0.25f, bin, s1);
    float u1 = fmaf(p0 + 0.75f, bin, s1);
    float v0 = ((u0 > -1.f) && (u0 < (float)DIM)) ? 0.5f : 0.f;
    float v1 = ((u1 > -1.f) && (u1 < (float)DIM)) ? 0.5f : 0.f;
    float c0 = fminf(fmaxf(u0, 0.f), (float)(DIM - 1));
    float c1 = fminf(fmaxf(u1, 0.f), (float)(DIM - 1));
    int i0 = (int)c0;
    int i1 = (int)c1;
    float l0 = (i0 >= DIM - 1) ? 1.f : c0 - (float)i0;
    float l1 = (i1 >= DIM - 1) ? 1.f : c1 - (float)i1;
    int a0 = min(i0, DIM - 2);
    int a1 = min(i1, DIM - 2);
    int e  = a1 - a0;                       // 0, 1, or 2
    float t00 = (1.f - l0) * v0, t01 = l0 * v0;
    float t10 = (1.f - l1) * v1, t11 = l1 * v1;
    w0 = t00 + ((e == 0) ? t10 : 0.f);
    w1 = t01 + ((e == 0) ? t11 : ((e == 1) ? t10 : 0.f));
    w2 = (e == 1) ? t11 : ((e == 2) ? t10 : 0.f);
    w3 = (e == 2) ? t11 : 0.f;
    base = a0;
    has4 = (e == 2);
}

__device__ __forceinline__ unsigned packh2(float lo, float hi) {
    __half2 h = __floats2half2_rn(lo, hi);
    return *(unsigned*)&h;
}
__device__ __forceinline__ __half2 splat_lo(unsigned u) {
    __half2 h = *(__half2*)&u;
    return __half2half2(__low2half(h));
}
__device__ __forceinline__ __half2 splat_hi(unsigned u) {
    __half2 h = *(__half2*)&u;
    return __half2half2(__high2half(h));
}

#define CTAP(ptr, cwh) do {                                                  \
    uint4 _v = __ldg(reinterpret_cast<const uint4*>(ptr));                   \
    const __half2* _h = reinterpret_cast<const __half2*>(&_v);               \
    q0 = __hfma2(cwh, _h[0], q0); q1 = __hfma2(cwh, _h[1], q1);              \
    q2 = __hfma2(cwh, _h[2], q2); q3 = __hfma2(cwh, _h[3], q3);              \
} while (0)

#define ROWCOMBINE(rwh) do {                                                 \
    a0 = __hfma2(rwh, q0, a0); a1 = __hfma2(rwh, q1, a1);                    \
    a2 = __hfma2(rwh, q2, a2); a3 = __hfma2(rwh, q3, a3);                    \
} while (0)

template <int P, int H, int W>
__device__ __forceinline__ void gather_level(
    const float* __restrict__ rois, float* __restrict__ out_lvl,
    unsigned lvl_off, float scale, int pxbase, int npx,
    unsigned* __restrict__ sacc)
{
    constexpr int pixels = P * P;
    int tid  = threadIdx.x;
    int wid  = tid >> 5;
    int lane = tid & 31;

    // ---- geometry phase: lane l handles pixel j = l&3 ----
    unsigned g_base, g_rw01, g_rw23, g_cw01, g_cw23, g_flags;
    int g_o2, g_ro1, g_ro2;
    {
        int jl  = lane & 3;
        int pxl = jl * 8 + wid;
        int gpx = pxbase + pxl;
        if (gpx < npx) {
            int n  = gpx / pixels;
            int p  = gpx - n * pixels;
            int ph = p / P;
            int pw = p - ph * P;
            const float* r = rois + n * 5;
            int   bi = (int)r[0];
            float x1 = fmaf(r[1], scale, -0.5f);
            float y1 = fmaf(r[2], scale, -0.5f);
            float bw = (fmaf(r[3], scale, -0.5f) - x1) * (1.0f / (float)P);
            float bh = (fmaf(r[4], scale, -0.5f) - y1) * (1.0f / (float)P);

            int ybase, xbase; bool ry4, cx4;
            float rw0, rw1, rw2, rw3, cw0, cw1, cw2, cw3;
            axis_weights<H>((float)ph, y1, bh, ybase, ry4, rw0, rw1, rw2, rw3);
            axis_weights<W>((float)pw, x1, bw, xbase, cx4, cw0, cw1, cw2, cw3);

            g_base = lvl_off + (unsigned)((bi * H * W + ybase * W + xbase) * NCH);
            g_rw01 = packh2(rw0, rw1); g_rw23 = packh2(rw2, rw3);
            g_cw01 = packh2(cw0, cw1); g_cw23 = packh2(cw2, cw3);
            bool fast = !ry4 && !cx4 && (xbase <= W - 3) && (ybase <= H - 3);
            g_flags = (fast ? 1u : 0u) | (cx4 ? 2u : 0u) | (ry4 ? 4u : 0u);
            g_o2  = (min(xbase + 2, W - 1) - xbase) * NCH;
            g_ro1 = (min(ybase + 1, H - 1) - ybase) * W * NCH;
            g_ro2 = (min(ybase + 2, H - 1) - ybase) * W * NCH;
        } else {
            g_base = lvl_off;        // safe window at level origin
            g_rw01 = g_rw23 = g_cw01 = g_cw23 = 0u;   // all weights 0
            g_flags = 1u;            // fast path
            g_o2 = g_ro1 = g_ro2 = 0;
        }
    }

    __half2 z = __float2half2_rn(0.f);

#pragma unroll
    for (int j = 0; j < 4; j++) {
        unsigned bo  = __shfl_sync(0xffffffffu, g_base,  j);
        unsigned rwp0 = __shfl_sync(0xffffffffu, g_rw01, j);
        unsigned rwp1 = __shfl_sync(0xffffffffu, g_rw23, j);
        unsigned cwp0 = __shfl_sync(0xffffffffu, g_cw01, j);
        unsigned cwp1 = __shfl_sync(0xffffffffu, g_cw23, j);
        unsigned fl  = __shfl_sync(0xffffffffu, g_flags, j);

        __half2 rw0 = splat_lo(rwp0), rw1 = splat_hi(rwp0);
        __half2 rw2 = splat_lo(rwp1), rw3 = splat_hi(rwp1);
        __half2 cw0 = splat_lo(cwp0), cw1 = splat_hi(cwp0);
        __half2 cw2 = splat_lo(cwp1), cw3 = splat_hi(cwp1);

        const __half* rp0 = g_nhwc + bo + lane * 8;
        __half2 a0 = z, a1 = z, a2 = z, a3 = z;

        if (fl & 1u) {
            // interior fast path: all offsets compile-time immediates
            {
                __half2 q0 = z, q1 = z, q2 = z, q3 = z;
                CTAP(rp0,           cw0);
                CTAP(rp0 + NCH,     cw1);
                CTAP(rp0 + 2 * NCH, cw2);
                ROWCOMBINE(rw0);
            }
            {
                const __half* rp = rp0 + W * NCH;
                __half2 q0 = z, q1 = z, q2 = z, q3 = z;
                CTAP(rp,           cw0);
                CTAP(rp + NCH,     cw1);
                CTAP(rp + 2 * NCH, cw2);
                ROWCOMBINE(rw1);
            }
            {
                const __half* rp = rp0 + 2 * W * NCH;
                __half2 q0 = z, q1 = z, q2 = z, q3 = z;
                CTAP(rp,           cw0);
                CTAP(rp + NCH,     cw1);
                CTAP(rp + 2 * NCH, cw2);
                ROWCOMBINE(rw2);
            }
        } else {
            int o2  = __shfl_sync(0xffffffffu, g_o2,  j);
            int ro1 = __shfl_sync(0xffffffffu, g_ro1, j);
            int ro2 = __shfl_sync(0xffffffffu, g_ro2, j);
            bool cx4 = (fl & 2u) != 0;
            bool ry4 = (fl & 4u) != 0;
            {
                __half2 q0 = z, q1 = z, q2 = z, q3 = z;
                CTAP(rp0,       cw0);
                CTAP(rp0 + NCH, cw1);
                CTAP(rp0 + o2,  cw2);
                if (cx4) CTAP(rp0 + 3 * NCH, cw3);
                ROWCOMBINE(rw0);
            }
            {
                const __half* rp = rp0 + ro1;
                __half2 q0 = z, q1 = z, q2 = z, q3 = z;
                CTAP(rp,       cw0);
                CTAP(rp + NCH, cw1);
                CTAP(rp + o2,  cw2);
                if (cx4) CTAP(rp + 3 * NCH, cw3);
                ROWCOMBINE(rw1);
            }
            {
                const __half* rp = rp0 + ro2;
                __half2 q0 = z, q1 = z, q2 = z, q3 = z;
                CTAP(rp,       cw0);
                CTAP(rp + NCH, cw1);
                CTAP(rp + o2,  cw2);
                if (cx4) CTAP(rp + 3 * NCH, cw3);
                ROWCOMBINE(rw2);
            }
            if (ry4) {
                const __half* rp = rp0 + 3 * W * NCH;
                __half2 q0 = z, q1 = z, q2 = z, q3 = z;
                CTAP(rp,       cw0);
                CTAP(rp + NCH, cw1);
                CTAP(rp + o2,  cw2);
                if (cx4) CTAP(rp + 3 * NCH, cw3);
                ROWCOMBINE(rw3);
            }
        }

        int pxl = j * 8 + wid;
        int col = pxl ^ lane;
        sacc[(4 * lane + 0) * 32 + col] = *(unsigned*)&a0;
        sacc[(4 * lane + 1) * 32 + col] = *(unsigned*)&a1;
        sacc[(4 * lane + 2) * 32 + col] = *(unsigned*)&a2;
        sacc[(4 * lane + 3) * 32 + col] = *(unsigned*)&a3;
    }
    __syncthreads();

    // store phase: lanes along pixels -> coalesced NCHW writes
    int pxlane = tid & 31;
    int gpx = pxbase + pxlane;
    if (gpx < npx) {
        int n = gpx / pixels;
        int p = gpx - n * pixels;
        float* ob = out_lvl + (size_t)n * NCH * pixels + p;
        int pp0 = (tid >> 5) * 16;
#pragma unroll
        for (int i = 0; i < 16; i++) {
            int pp = pp0 + i;
            unsigned u = sacc[pp * 32 + (pxlane ^ (pp >> 2))];
            __half2 h = *(__half2*)&u;
            int c = 2 * pp;
            ob[(size_t)c       * pixels] = __low2float(h);
            ob[(size_t)(c + 1) * pixels] = __high2float(h);
        }
    }
}

__global__ void __launch_bounds__(256)
roi_gather_kernel(const float* __restrict__ rois, float* __restrict__ out,
                  int N, int nb1, int nb2)
{
    __shared__ unsigned sacc[128 * 32];   // 16KB
    int blk = blockIdx.x;
    if (blk < nb1) {
        gather_level<28, 256, 256>(rois, out, 0u, 0.25f,
                                   blk * 32, N * 784, sacc);
    } else if (blk < nb1 + nb2) {
        float* o2 = out + (size_t)N * NCH * 784;
        gather_level<14, 128, 128>(rois, o2, 33554432u, 0.125f,
                                   (blk - nb1) * 32, N * 196, sacc);
    } else {
        float* o3 = out + (size_t)N * NCH * (784 + 196);
        gather_level<7, 64, 64>(rois, o3, 41943040u, 0.0625f,
                                (blk - nb1 - nb2) * 32, N * 49, sacc);
    }
}

// ---------------------------------------------------------------------------
extern "C" void kernel_launch(void* const* d_in, const int* in_sizes, int n_in,
                              void* d_out, int out_size)
{
    const float* feat1 = (const float*)d_in[0];  // (2,256,256,256)
    const float* feat2 = (const float*)d_in[1];  // (2,256,128,128)
    const float* feat3 = (const float*)d_in[2];  // (2,256,64,64)
    const float* rois  = (const float*)d_in[3];  // (N,5)
    float* out = (float*)d_out;

    const int N = in_sizes[3] / 5;

    // 1) fused transpose: 16384 (L1) + 4096 (L2) + 1024 (L3) blocks
    nchw_to_nhwc_fused<<<21504, 256>>>(feat1, feat2, feat3);

    // 2) fused gather over all three levels
    int nb1 = (N * 784 + 31) / 32;
    int nb2 = (N * 196 + 31) / 32;
    int nb3 = (N * 49  + 31) / 32;
    roi_gather_kernel<<<nb1 + nb2 + nb3, 256>>>(rois, out, N, nb1, nb2);
}